// round 6
// baseline (speedup 1.0000x reference)
#include <cuda_runtime.h>
#include <cuda_bf16.h>
#include <math.h>
#include <stdint.h>

// ---------------------------------------------------------------------------
// Problem constants
// ---------------------------------------------------------------------------
constexpr int B     = 4;
constexpr int S     = 2048;
constexpr int EMBED = 2048;
constexpr int DC    = 512;     // D_COMPR
constexpr int DR    = 128;     // D_ROPE
constexpr int DCC   = DC - DR; // 384
constexpr int H     = 8;
constexpr int HD    = 64;      // head dim
constexpr int M     = B * S;   // 8192 rows

// weight-plane offsets (elements) inside g_wh / g_wl
constexpr size_t OFF_Q   = 0;
constexpr size_t OFF_KV  = OFF_Q   + 512 * 2048;
constexpr size_t OFF_QR  = OFF_KV  + 512 * 2048;
constexpr size_t OFF_KR  = OFF_QR  + 128 * 2048;
constexpr size_t OFF_QC  = OFF_KR  + 128 * 2048;
constexpr size_t OFF_KC  = OFF_QC  + 384 * 512;
constexpr size_t OFF_V   = OFF_KC  + 384 * 512;
constexpr size_t OFF_OUT = OFF_V   + 512 * 512;
constexpr size_t W_TOTAL = OFF_OUT + 2048 * 512;

// ---------------------------------------------------------------------------
// Scratch (device globals; allocation is forbidden)
// ---------------------------------------------------------------------------
__device__ __align__(16) __nv_bfloat16 g_xh[(size_t)M * 2048];
__device__ __align__(16) __nv_bfloat16 g_xl[(size_t)M * 2048];
__device__ __align__(16) __nv_bfloat16 g_wh[W_TOTAL];
__device__ __align__(16) __nv_bfloat16 g_wl[W_TOTAL];
__device__ __align__(16) __nv_bfloat16 g_cqkvh[(size_t)M * 1024];
__device__ __align__(16) __nv_bfloat16 g_cqkvl[(size_t)M * 1024];
__device__ __align__(16) __nv_bfloat16 g_qh[(size_t)M * 512];
__device__ __align__(16) __nv_bfloat16 g_ql[(size_t)M * 512];
__device__ __align__(16) __nv_bfloat16 g_kh[(size_t)M * 512];
__device__ __align__(16) __nv_bfloat16 g_kl[(size_t)M * 512];
__device__ __align__(16) __nv_bfloat16 g_vh[(size_t)M * 512];
__device__ __align__(16) __nv_bfloat16 g_vl[(size_t)M * 512];
__device__ __align__(16) __nv_bfloat16 g_oh[(size_t)M * 512];
__device__ __align__(16) __nv_bfloat16 g_ol[(size_t)M * 512];
__device__ float g_qr [M * 256];       // cols 0-127: cqr, 128-255: ckr (pre-rope)

__device__ __forceinline__ float gelu_exact(float v) {
    return 0.5f * v * (1.0f + erff(v * 0.70710678118654752f));
}

// fp32 pair -> bf16x2 hi + bf16x2 lo residual
__device__ __forceinline__ void cvt_pair(float e0, float e1,
                                         uint32_t& h, uint32_t& l) {
    asm("cvt.rn.bf16x2.f32 %0, %1, %2;" : "=r"(h) : "f"(e1), "f"(e0));
    float h0 = __uint_as_float(h << 16);
    float h1 = __uint_as_float(h & 0xFFFF0000u);
    asm("cvt.rn.bf16x2.f32 %0, %1, %2;" : "=r"(l) : "f"(e1 - h1), "f"(e0 - h0));
}

// FMA-pipe exp (no MUFU): exp(x) for x <= 0, clamped at -80.
__device__ __forceinline__ float fast_exp(float x) {
    x = fmaxf(x, -80.0f);
    float t = fmaf(x, 1.4426950408889634f, 12582912.0f);
    float i = t - 12582912.0f;
    float f = fmaf(x, 1.4426950408889634f, -i);
    float p = 1.3333558146e-3f;
    p = fmaf(p, f, 9.6181291076e-3f);
    p = fmaf(p, f, 5.5504108665e-2f);
    p = fmaf(p, f, 2.4022650696e-1f);
    p = fmaf(p, f, 6.9314718056e-1f);
    p = fmaf(p, f, 1.0f);
    return __int_as_float(__float_as_int(p) +
                          ((__float_as_int(t) - 0x4B400000) << 23));
}

__device__ __forceinline__ uint32_t smem_u32(const void* p) {
    uint32_t a;
    asm("{ .reg .u64 t; cvta.to.shared.u64 t, %1; cvt.u32.u64 %0, t; }"
        : "=r"(a) : "l"(p));
    return a;
}

#define CP16(dst, src) \
    asm volatile("cp.async.cg.shared.global [%0], [%1], 16;" \
                 :: "r"(dst), "l"(src) : "memory")
#define CP_COMMIT() asm volatile("cp.async.commit_group;" ::: "memory")
#define CP_WAIT1()  asm volatile("cp.async.wait_group 1;" ::: "memory")
#define CP_WAIT0()  asm volatile("cp.async.wait_group 0;" ::: "memory")

#define LDSM4(r0, r1, r2, r3, addr) \
    asm volatile("ldmatrix.sync.aligned.m8n8.x4.shared.b16 {%0,%1,%2,%3}, [%4];" \
                 : "=r"(r0), "=r"(r1), "=r"(r2), "=r"(r3) : "r"(addr))
#define LDSM4T(r0, r1, r2, r3, addr) \
    asm volatile("ldmatrix.sync.aligned.m8n8.x4.trans.shared.b16 {%0,%1,%2,%3}, [%4];" \
                 : "=r"(r0), "=r"(r1), "=r"(r2), "=r"(r3) : "r"(addr))

#define MMA_BF16(d, a, b) \
    asm volatile("mma.sync.aligned.m16n8k16.row.col.f32.bf16.bf16.f32 " \
                 "{%0,%1,%2,%3},{%4,%5,%6,%7},{%8,%9},{%0,%1,%2,%3};" \
                 : "+f"((d)[0]), "+f"((d)[1]), "+f"((d)[2]), "+f"((d)[3]) \
                 : "r"((a)[0]), "r"((a)[1]), "r"((a)[2]), "r"((a)[3]), \
                   "r"((b)[0]), "r"((b)[1]))

// ---------------------------------------------------------------------------
// fp32 -> bf16 hi/lo planes
// ---------------------------------------------------------------------------
__global__ void cvt_planes(const float* __restrict__ src,
                           __nv_bfloat16* __restrict__ h,
                           __nv_bfloat16* __restrict__ l, int n4) {
    int i = blockIdx.x * blockDim.x + threadIdx.x;
    if (i >= n4) return;
    float4 v = ((const float4*)src)[i];
    uint32_t h0, h1, l0, l1;
    cvt_pair(v.x, v.y, h0, l0);
    cvt_pair(v.z, v.w, h1, l1);
    ((uint2*)h)[i] = make_uint2(h0, h1);
    ((uint2*)l)[i] = make_uint2(l0, l1);
}

// ---------------------------------------------------------------------------
// Fused multi-tile GEMM via mma.sync (bf16 hi/lo split, fp32 accumulate)
// Each blockIdx.x selects a 128-column tile described by TileP (its own A,
// W, bias, outputs, and epilogue mode). blockIdx.y tiles M in 128-row steps.
// mode bits: 1 = GELU, 2 = write fp32 C, 4 = write bf16 hi/lo planes.
// scale multiplies after GELU (used to fold 1/sqrt(d) into Q).
// ---------------------------------------------------------------------------
struct TileP {
    const __nv_bfloat16 *Ah, *Al, *Wh, *Wl;
    const float* bias;
    float* Cf;
    __nv_bfloat16 *Ch, *Cl;
    int lda, ldc, ldh, mode;
    float scale;
};
struct TileArr16 { TileP t[16]; };

constexpr int SM_AH = 0;
constexpr int SM_AL = 10240;
constexpr int SM_BH = 20480;
constexpr int SM_BL = 30720;
constexpr int SM_STAGE = 40960;
constexpr int GEMM_SMEM = 2 * SM_STAGE;

__global__ void __launch_bounds__(256)
gemm_tiles(TileArr16 ta, int K) {
    const TileP tp = ta.t[blockIdx.x];

    extern __shared__ char smem[];
    const uint32_t sb = smem_u32(smem);

    const int tid    = threadIdx.x;
    const int lane   = tid & 31;
    const int wid    = tid >> 5;
    const int warp_m = wid >> 2;
    const int warp_n = wid & 3;
    const int bm     = blockIdx.y * 128;

    const int lrow  = tid >> 1;
    const int lsegE = (tid & 1) * 16;
    const int lsegB = (tid & 1) * 32;

    const __nv_bfloat16* gAh = tp.Ah + (size_t)(bm + lrow) * tp.lda + lsegE;
    const __nv_bfloat16* gAl = tp.Al + (size_t)(bm + lrow) * tp.lda + lsegE;
    const __nv_bfloat16* gWh = tp.Wh + (size_t)lrow * K + lsegE;
    const __nv_bfloat16* gWl = tp.Wl + (size_t)lrow * K + lsegE;
    const uint32_t srowA = lrow * 80 + lsegB;

    const uint32_t aBase = (uint32_t)((warp_m * 64 + (lane & 15)) * 80 +
                                      ((lane >> 4) << 4));
    const uint32_t bBase = (uint32_t)((warp_n * 32 + (lane & 7) +
                                       ((lane & 16) >> 1)) * 80 +
                                      (((lane >> 3) & 1) << 4));

    float d[4][4][4];
    #pragma unroll
    for (int i = 0; i < 4; ++i)
        #pragma unroll
        for (int j = 0; j < 4; ++j)
            #pragma unroll
            for (int k = 0; k < 4; ++k) d[i][j][k] = 0.0f;

    auto load_stage = [&](int s, int kt) {
        const uint32_t sbase = sb + s * SM_STAGE + srowA;
        const int ge = kt * 32;
        CP16(sbase + SM_AH,      gAh + ge);
        CP16(sbase + SM_AH + 16, gAh + ge + 8);
        CP16(sbase + SM_AL,      gAl + ge);
        CP16(sbase + SM_AL + 16, gAl + ge + 8);
        CP16(sbase + SM_BH,      gWh + ge);
        CP16(sbase + SM_BH + 16, gWh + ge + 8);
        CP16(sbase + SM_BL,      gWl + ge);
        CP16(sbase + SM_BL + 16, gWl + ge + 8);
    };

    const int KT = K >> 5;
    load_stage(0, 0); CP_COMMIT();
    load_stage(1, 1); CP_COMMIT();

    for (int kt = 0; kt < KT; ++kt) {
        CP_WAIT1();
        __syncthreads();

        const uint32_t stage = sb + (kt & 1) * SM_STAGE;
        #pragma unroll
        for (int k16 = 0; k16 < 2; ++k16) {
            uint32_t ah[4][4], al[4][4], bh[4][2], bl[4][2];
            #pragma unroll
            for (int mt = 0; mt < 4; ++mt) {
                uint32_t addr = stage + aBase + mt * (16 * 80) + k16 * 32;
                LDSM4(ah[mt][0], ah[mt][1], ah[mt][2], ah[mt][3], addr + SM_AH);
                LDSM4(al[mt][0], al[mt][1], al[mt][2], al[mt][3], addr + SM_AL);
            }
            #pragma unroll
            for (int np = 0; np < 2; ++np) {
                uint32_t addr = stage + bBase + np * (16 * 80) + k16 * 32;
                LDSM4(bh[2*np][0], bh[2*np][1], bh[2*np+1][0], bh[2*np+1][1],
                      addr + SM_BH);
                LDSM4(bl[2*np][0], bl[2*np][1], bl[2*np+1][0], bl[2*np+1][1],
                      addr + SM_BL);
            }
            #pragma unroll
            for (int mt = 0; mt < 4; ++mt)
                #pragma unroll
                for (int nt = 0; nt < 4; ++nt) {
                    MMA_BF16(d[mt][nt], ah[mt], bh[nt]);
                    MMA_BF16(d[mt][nt], ah[mt], bl[nt]);
                    MMA_BF16(d[mt][nt], al[mt], bh[nt]);
                }
        }
        __syncthreads();
        if (kt + 2 < KT) load_stage(kt & 1, kt + 2);
        CP_COMMIT();
    }

    // ------------------------- epilogue -------------------------
    const int grp  = lane >> 2;
    const int qd   = lane & 3;
    const int mode = tp.mode;
    const float sc = tp.scale;
    #pragma unroll
    for (int mt = 0; mt < 4; ++mt) {
        const int r0 = bm + warp_m * 64 + mt * 16 + grp;
        const int r1 = r0 + 8;
        #pragma unroll
        for (int nt = 0; nt < 4; ++nt) {
            const int col = warp_n * 32 + nt * 8 + qd * 2;
            float2 bb = *(const float2*)&tp.bias[col];
            float v00 = d[mt][nt][0] + bb.x;
            float v01 = d[mt][nt][1] + bb.y;
            float v10 = d[mt][nt][2] + bb.x;
            float v11 = d[mt][nt][3] + bb.y;
            if (mode & 1) {
                v00 = gelu_exact(v00); v01 = gelu_exact(v01);
                v10 = gelu_exact(v10); v11 = gelu_exact(v11);
            }
            v00 *= sc; v01 *= sc; v10 *= sc; v11 *= sc;
            if (mode & 2) {
                *(float2*)&tp.Cf[(size_t)r0 * tp.ldc + col] = make_float2(v00, v01);
                *(float2*)&tp.Cf[(size_t)r1 * tp.ldc + col] = make_float2(v10, v11);
            }
            if (mode & 4) {
                uint32_t h, l;
                cvt_pair(v00, v01, h, l);
                *(uint32_t*)&tp.Ch[(size_t)r0 * tp.ldh + col] = h;
                *(uint32_t*)&tp.Cl[(size_t)r0 * tp.ldh + col] = l;
                cvt_pair(v10, v11, h, l);
                *(uint32_t*)&tp.Ch[(size_t)r1 * tp.ldh + col] = h;
                *(uint32_t*)&tp.Cl[(size_t)r1 * tp.ldh + col] = l;
            }
        }
    }
}

// ---------------------------------------------------------------------------
// Rope-only plane builder for Q/K columns [384, 512).
// One thread per (m, even j); computes sincos once, applies to Q and K.
// ---------------------------------------------------------------------------
__global__ void rope_planes(const float* __restrict__ qr,
                            __nv_bfloat16* __restrict__ qh, __nv_bfloat16* __restrict__ ql,
                            __nv_bfloat16* __restrict__ kh, __nv_bfloat16* __restrict__ kl) {
    int idx = blockIdx.x * blockDim.x + threadIdx.x;   // M*64
    if (idx >= M * 64) return;
    int m  = idx >> 6;
    int jp = (idx & 63) * 2;        // even j, pair (jp, jp+1) never crosses 64
    int s  = m & (S - 1);

    float vq[2], vk[2];
    #pragma unroll
    for (int e = 0; e < 2; ++e) {
        int jj = jp + e;
        int i  = jj & 63;
        float invf = expf(-(float)i * (9.2103403719761836f / 64.0f));
        float ang  = (float)s * invf;
        float sv, cv; sincosf(ang, &sv, &cv);
        float xq = qr[m * 256 + jj];
        float xk = qr[m * 256 + 128 + jj];
        float rq, rk;
        if (jj < 64) { rq = -qr[m * 256 + jj + 64]; rk = -qr[m * 256 + 128 + jj + 64]; }
        else         { rq =  qr[m * 256 + jj - 64]; rk =  qr[m * 256 + 128 + jj - 64]; }
        vq[e] = gelu_exact(xq * cv + rq * sv) * 0.125f;
        vk[e] = gelu_exact(xk * cv + rk * sv);
    }
    uint32_t h, l;
    size_t o = (size_t)m * DC + DCC + jp;
    cvt_pair(vq[0], vq[1], h, l);
    *(uint32_t*)&qh[o] = h; *(uint32_t*)&ql[o] = l;
    cvt_pair(vk[0], vk[1], h, l);
    *(uint32_t*)&kh[o] = h; *(uint32_t*)&kl[o] = l;
}

// ---------------------------------------------------------------------------
// Flash attention via mma.sync, register-resident softmax.
// grid = (S/128, H, B), 256 threads. qt reversed for load balance.
// ---------------------------------------------------------------------------
constexpr int AT_QH   = 0;
constexpr int AT_QL   = 18432;
constexpr int AT_ST0  = 36864;
constexpr int AT_KH   = 0;
constexpr int AT_KL   = 9216;
constexpr int AT_VH   = 18432;
constexpr int AT_VL   = 27648;
constexpr int AT_STSZ = 36864;
constexpr int ATTN_SMEM = AT_ST0 + 2 * AT_STSZ;

__global__ void __launch_bounds__(256)
attn_mma(const __nv_bfloat16* __restrict__ Qh, const __nv_bfloat16* __restrict__ Ql,
         const __nv_bfloat16* __restrict__ Kh, const __nv_bfloat16* __restrict__ Kl,
         const __nv_bfloat16* __restrict__ Vh, const __nv_bfloat16* __restrict__ Vl,
         __nv_bfloat16* __restrict__ Oh, __nv_bfloat16* __restrict__ Ol) {
    extern __shared__ char smem[];
    const uint32_t sb = smem_u32(smem);

    const int qt = gridDim.x - 1 - blockIdx.x;   // heavy tiles first
    const int h = blockIdx.y, b = blockIdx.z;
    const int q0 = qt * 128;
    const int tid  = threadIdx.x;
    const int lane = tid & 31;
    const int wid  = tid >> 5;
    const int m0   = wid * 16;
    const int grp  = lane >> 2;
    const int qd   = lane & 3;
    const int bS   = b * S;
    const size_t hoff = (size_t)h * HD;

    {
        int r  = tid >> 1;
        int ch = (tid & 1) * 4;
        size_t g = (size_t)(bS + q0 + r) * DC + hoff + ch * 8;
        uint32_t sdst = sb + AT_QH + r * 144 + ch * 16;
        #pragma unroll
        for (int c = 0; c < 4; ++c) {
            CP16(sdst + c * 16,         Qh + g + c * 8);
            CP16(sdst + 18432 + c * 16, Ql + g + c * 8);
        }
    }
    auto load_kv = [&](int kt, int buf) {
        const uint32_t stage = sb + AT_ST0 + buf * AT_STSZ;
        int r  = tid >> 2;
        int ch = (tid & 3) * 2;
        size_t g = (size_t)(bS + kt * 64 + r) * DC + hoff + ch * 8;
        uint32_t sdst = stage + r * 144 + ch * 16;
        #pragma unroll
        for (int c = 0; c < 2; ++c) {
            CP16(sdst + AT_KH + c * 16, Kh + g + c * 8);
            CP16(sdst + AT_KL + c * 16, Kl + g + c * 8);
            CP16(sdst + AT_VH + c * 16, Vh + g + c * 8);
            CP16(sdst + AT_VL + c * 16, Vl + g + c * 8);
        }
    };
    load_kv(0, 0);
    CP_COMMIT();

    float mrow[2] = {-1e30f, -1e30f};
    float lrow[2] = {0.0f, 0.0f};
    float acc[8][4];
    #pragma unroll
    for (int j = 0; j < 8; ++j)
        #pragma unroll
        for (int c = 0; c < 4; ++c) acc[j][c] = 0.0f;

    const uint32_t aBase = sb + AT_QH + (m0 + (lane & 15)) * 144 +
                           ((lane >> 4) << 4);
    const uint32_t bRow  = ((lane & 7) + ((lane & 16) >> 1)) * 144 +
                           (((lane >> 3) & 1) << 4);
    const uint32_t vRow  = (lane & 15) * 144 + ((lane >> 4) << 4);

    const int kt_end = 2 * qt + 1;
    for (int kt = 0; kt <= kt_end; ++kt) {
        CP_WAIT0();
        __syncthreads();
        if (kt < kt_end) { load_kv(kt + 1, (kt + 1) & 1); }
        CP_COMMIT();

        const uint32_t stage = sb + AT_ST0 + (kt & 1) * AT_STSZ;
        const int k0 = kt * 64;

        float s[8][4];
        #pragma unroll
        for (int j = 0; j < 8; ++j)
            #pragma unroll
            for (int c = 0; c < 4; ++c) s[j][c] = 0.0f;

        #pragma unroll
        for (int k16 = 0; k16 < 4; ++k16) {
            uint32_t qh[4], ql[4];
            LDSM4(qh[0], qh[1], qh[2], qh[3], aBase + k16 * 32);
            LDSM4(ql[0], ql[1], ql[2], ql[3], aBase + 18432 + k16 * 32);
            #pragma unroll
            for (int np = 0; np < 4; ++np) {
                uint32_t kh[4], kl[4];
                uint32_t baddr = stage + bRow + np * (16 * 144) + k16 * 32;
                LDSM4(kh[0], kh[1], kh[2], kh[3], baddr + AT_KH);
                LDSM4(kl[0], kl[1], kl[2], kl[3], baddr + AT_KL);
                MMA_BF16(s[2*np],   qh, kh);
                MMA_BF16(s[2*np],   qh, kl);
                MMA_BF16(s[2*np],   ql, kh);
                MMA_BF16(s[2*np+1], qh, kh + 2);
                MMA_BF16(s[2*np+1], qh, kl + 2);
                MMA_BF16(s[2*np+1], ql, kh + 2);
            }
        }

        const int row0 = q0 + m0 + grp;
        if (k0 + 63 > q0 + m0) {
            #pragma unroll
            for (int j = 0; j < 8; ++j) {
                int kg = k0 + j * 8 + qd * 2;
                if (kg     > row0)     s[j][0] = -1e30f;
                if (kg + 1 > row0)     s[j][1] = -1e30f;
                if (kg     > row0 + 8) s[j][2] = -1e30f;
                if (kg + 1 > row0 + 8) s[j][3] = -1e30f;
            }
        }

        float mx0 = -1e30f, mx1 = -1e30f;
        #pragma unroll
        for (int j = 0; j < 8; ++j) {
            mx0 = fmaxf(mx0, fmaxf(s[j][0], s[j][1]));
            mx1 = fmaxf(mx1, fmaxf(s[j][2], s[j][3]));
        }
        mx0 = fmaxf(mx0, __shfl_xor_sync(0xFFFFFFFF, mx0, 1));
        mx0 = fmaxf(mx0, __shfl_xor_sync(0xFFFFFFFF, mx0, 2));
        mx1 = fmaxf(mx1, __shfl_xor_sync(0xFFFFFFFF, mx1, 1));
        mx1 = fmaxf(mx1, __shfl_xor_sync(0xFFFFFFFF, mx1, 2));
        float mn0 = fmaxf(mrow[0], mx0);
        float mn1 = fmaxf(mrow[1], mx1);
        float al0 = fast_exp(mrow[0] - mn0);
        float al1 = fast_exp(mrow[1] - mn1);
        mrow[0] = mn0; mrow[1] = mn1;

        float sum0 = 0.0f, sum1 = 0.0f;
        #pragma unroll
        for (int j = 0; j < 8; ++j) {
            s[j][0] = fast_exp(s[j][0] - mn0); sum0 += s[j][0];
            s[j][1] = fast_exp(s[j][1] - mn0); sum0 += s[j][1];
            s[j][2] = fast_exp(s[j][2] - mn1); sum1 += s[j][2];
            s[j][3] = fast_exp(s[j][3] - mn1); sum1 += s[j][3];
        }
        sum0 += __shfl_xor_sync(0xFFFFFFFF, sum0, 1);
        sum0 += __shfl_xor_sync(0xFFFFFFFF, sum0, 2);
        sum1 += __shfl_xor_sync(0xFFFFFFFF, sum1, 1);
        sum1 += __shfl_xor_sync(0xFFFFFFFF, sum1, 2);
        lrow[0] = lrow[0] * al0 + sum0;
        lrow[1] = lrow[1] * al1 + sum1;

        #pragma unroll
        for (int j = 0; j < 8; ++j) {
            acc[j][0] *= al0; acc[j][1] *= al0;
            acc[j][2] *= al1; acc[j][3] *= al1;
        }

        #pragma unroll
        for (int k2 = 0; k2 < 4; ++k2) {
            uint32_t pah[4], pal[4];
            cvt_pair(s[2*k2][0],   s[2*k2][1],   pah[0], pal[0]);
            cvt_pair(s[2*k2][2],   s[2*k2][3],   pah[1], pal[1]);
            cvt_pair(s[2*k2+1][0], s[2*k2+1][1], pah[2], pal[2]);
            cvt_pair(s[2*k2+1][2], s[2*k2+1][3], pah[3], pal[3]);
            #pragma unroll
            for (int np = 0; np < 4; ++np) {
                uint32_t vh[4], vl[4];
                uint32_t vaddr = stage + vRow + k2 * (16 * 144) + np * 32;
                LDSM4T(vh[0], vh[1], vh[2], vh[3], vaddr + AT_VH);
                LDSM4T(vl[0], vl[1], vl[2], vl[3], vaddr + AT_VL);
                MMA_BF16(acc[2*np],   pah, vh);
                MMA_BF16(acc[2*np],   pah, vl);
                MMA_BF16(acc[2*np],   pal, vh);
                MMA_BF16(acc[2*np+1], pah, vh + 2);
                MMA_BF16(acc[2*np+1], pah, vl + 2);
                MMA_BF16(acc[2*np+1], pal, vh + 2);
            }
        }
    }

    const float inv0 = 1.0f / lrow[0];
    const float inv1 = 1.0f / lrow[1];
    const int row0 = q0 + m0 + grp;
    const size_t ob0 = (size_t)(bS + row0) * DC + hoff;
    const size_t ob1 = (size_t)(bS + row0 + 8) * DC + hoff;
    #pragma unroll
    for (int j = 0; j < 8; ++j) {
        int col = j * 8 + qd * 2;
        uint32_t hh, ll;
        cvt_pair(acc[j][0] * inv0, acc[j][1] * inv0, hh, ll);
        *(uint32_t*)&Oh[ob0 + col] = hh;
        *(uint32_t*)&Ol[ob0 + col] = ll;
        cvt_pair(acc[j][2] * inv1, acc[j][3] * inv1, hh, ll);
        *(uint32_t*)&Oh[ob1 + col] = hh;
        *(uint32_t*)&Ol[ob1 + col] = ll;
    }
}

// ---------------------------------------------------------------------------
// Launch
// ---------------------------------------------------------------------------
extern "C" void kernel_launch(void* const* d_in, const int* in_sizes, int n_in,
                              void* d_out, int out_size) {
    const float* x     = (const float*)d_in[0];
    const float* CQ_w  = (const float*)d_in[1];
    const float* CQ_b  = (const float*)d_in[2];
    const float* CQC_w = (const float*)d_in[3];
    const float* CQC_b = (const float*)d_in[4];
    const float* CQR_w = (const float*)d_in[5];
    const float* CQR_b = (const float*)d_in[6];
    const float* CKV_w = (const float*)d_in[7];
    const float* CKV_b = (const float*)d_in[8];
    const float* CKR_w = (const float*)d_in[9];
    const float* CKR_b = (const float*)d_in[10];
    const float* CKC_w = (const float*)d_in[11];
    const float* CKC_b = (const float*)d_in[12];
    const float* CV_w  = (const float*)d_in[13];
    const float* CV_b  = (const float*)d_in[14];
    const float* OUT_w = (const float*)d_in[15];
    const float* OUT_b = (const float*)d_in[16];
    float* out = (float*)d_out;

    __nv_bfloat16 *xh, *xl, *wh, *wl, *cqkvh, *cqkvl;
    __nv_bfloat16 *qh, *ql, *kh, *kl, *vh, *vl, *oh, *ol;
    float *qr;
    cudaGetSymbolAddress((void**)&xh,    g_xh);
    cudaGetSymbolAddress((void**)&xl,    g_xl);
    cudaGetSymbolAddress((void**)&wh,    g_wh);
    cudaGetSymbolAddress((void**)&wl,    g_wl);
    cudaGetSymbolAddress((void**)&cqkvh, g_cqkvh);
    cudaGetSymbolAddress((void**)&cqkvl, g_cqkvl);
    cudaGetSymbolAddress((void**)&qh,    g_qh);
    cudaGetSymbolAddress((void**)&ql,    g_ql);
    cudaGetSymbolAddress((void**)&kh,    g_kh);
    cudaGetSymbolAddress((void**)&kl,    g_kl);
    cudaGetSymbolAddress((void**)&vh,    g_vh);
    cudaGetSymbolAddress((void**)&vl,    g_vl);
    cudaGetSymbolAddress((void**)&oh,    g_oh);
    cudaGetSymbolAddress((void**)&ol,    g_ol);
    cudaGetSymbolAddress((void**)&qr,    g_qr);

    cudaFuncSetAttribute(gemm_tiles,
                         cudaFuncAttributeMaxDynamicSharedMemorySize, GEMM_SMEM);
    cudaFuncSetAttribute(attn_mma,
                         cudaFuncAttributeMaxDynamicSharedMemorySize, ATTN_SMEM);

    auto cvt = [&](const float* src, __nv_bfloat16* h, __nv_bfloat16* l, size_t n) {
        int n4 = (int)(n / 4);
        cvt_planes<<<(n4 + 255) / 256, 256>>>(src, h, l, n4);
    };
    cvt(x,     xh,           xl,           (size_t)M * 2048);
    cvt(CQ_w,  wh + OFF_Q,   wl + OFF_Q,   512 * 2048);
    cvt(CKV_w, wh + OFF_KV,  wl + OFF_KV,  512 * 2048);
    cvt(CQR_w, wh + OFF_QR,  wl + OFF_QR,  128 * 2048);
    cvt(CKR_w, wh + OFF_KR,  wl + OFF_KR,  128 * 2048);
    cvt(CQC_w, wh + OFF_QC,  wl + OFF_QC,  384 * 512);
    cvt(CKC_w, wh + OFF_KC,  wl + OFF_KC,  384 * 512);
    cvt(CV_w,  wh + OFF_V,   wl + OFF_V,   512 * 512);
    cvt(OUT_w, wh + OFF_OUT, wl + OFF_OUT, 2048 * 512);

    dim3 blk(256);
    const int GY = M / 128;   // 64

    auto mkTile = [](const __nv_bfloat16* Ah, const __nv_bfloat16* Al, int lda,
                     const __nv_bfloat16* Wh, const __nv_bfloat16* Wl,
                     const float* bias, float* Cf, int ldc,
                     __nv_bfloat16* Ch, __nv_bfloat16* Cl, int ldh,
                     int mode, float scale) {
        TileP t;
        t.Ah = Ah; t.Al = Al; t.Wh = Wh; t.Wl = Wl; t.bias = bias;
        t.Cf = Cf; t.Ch = Ch; t.Cl = Cl;
        t.lda = lda; t.ldc = ldc; t.ldh = ldh; t.mode = mode; t.scale = scale;
        return t;
    };

    // ---------- Launch A: CQ | CKV | CQR | CKR  (K = 2048, 10 tiles) --------
    {
        TileArr16 ta;
        for (int t = 0; t < 4; ++t)   // cq -> cqkv cols [0,512)
            ta.t[t] = mkTile(xh, xl, 2048,
                             wh + OFF_Q + (size_t)t*128*2048, wl + OFF_Q + (size_t)t*128*2048,
                             CQ_b + t*128, nullptr, 0,
                             cqkvh + t*128, cqkvl + t*128, 1024, 1|4, 1.0f);
        for (int t = 0; t < 4; ++t)   // ckv -> cqkv cols [512,1024)
            ta.t[4+t] = mkTile(xh, xl, 2048,
                             wh + OFF_KV + (size_t)t*128*2048, wl + OFF_KV + (size_t)t*128*2048,
                             CKV_b + t*128, nullptr, 0,
                             cqkvh + 512 + t*128, cqkvl + 512 + t*128, 1024, 1|4, 1.0f);
        ta.t[8] = mkTile(xh, xl, 2048, wh + OFF_QR, wl + OFF_QR,
                         CQR_b, qr, 256, nullptr, nullptr, 0, 2, 1.0f);
        ta.t[9] = mkTile(xh, xl, 2048, wh + OFF_KR, wl + OFF_KR,
                         CKR_b, qr + 128, 256, nullptr, nullptr, 0, 2, 1.0f);
        gemm_tiles<<<dim3(10, GY), blk, GEMM_SMEM>>>(ta, 2048);
    }

    // ---------- Launch B: CQC | CKC | CV  (K = 512, 10 tiles) --------------
    {
        TileArr16 ta;
        for (int t = 0; t < 3; ++t)   // cqc -> Q planes cols [0,384), gelu*0.125
            ta.t[t] = mkTile(cqkvh, cqkvl, 1024,
                             wh + OFF_QC + (size_t)t*128*512, wl + OFF_QC + (size_t)t*128*512,
                             CQC_b + t*128, nullptr, 0,
                             qh + t*128, ql + t*128, 512, 1|4, 0.125f);
        for (int t = 0; t < 3; ++t)   // ckc -> K planes cols [0,384), gelu
            ta.t[3+t] = mkTile(cqkvh + 512, cqkvl + 512, 1024,
                             wh + OFF_KC + (size_t)t*128*512, wl + OFF_KC + (size_t)t*128*512,
                             CKC_b + t*128, nullptr, 0,
                             kh + t*128, kl + t*128, 512, 1|4, 1.0f);
        for (int t = 0; t < 4; ++t)   // V planes (no gelu)
            ta.t[6+t] = mkTile(cqkvh + 512, cqkvl + 512, 1024,
                             wh + OFF_V + (size_t)t*128*512, wl + OFF_V + (size_t)t*128*512,
                             CV_b + t*128, nullptr, 0,
                             vh + t*128, vl + t*128, 512, 4, 1.0f);
        gemm_tiles<<<dim3(10, GY), blk, GEMM_SMEM>>>(ta, 512);
    }

    // rope columns [384,512) of Q/K planes
    rope_planes<<<(M * 64 + 255) / 256, 256>>>(qr, qh, ql, kh, kl);

    // causal flash attention -> O planes
    attn_mma<<<dim3(S/128, H, B), blk, ATTN_SMEM>>>(qh, ql, kh, kl, vh, vl, oh, ol);

    // ---------- Launch C: OUT  (K = 512, 16 tiles) --------------------------
    {
        TileArr16 ta;
        for (int t = 0; t < 16; ++t)
            ta.t[t] = mkTile(oh, ol, 512,
                             wh + OFF_OUT + (size_t)t*128*512, wl + OFF_OUT + (size_t)t*128*512,
                             OUT_b + t*128, out + t*128, 2048,
                             nullptr, nullptr, 0, 2, 1.0f);
        gemm_tiles<<<dim3(16, GY), blk, GEMM_SMEM>>>(ta, 512);
    }
}